// round 1
// baseline (speedup 1.0000x reference)
#include <cuda_runtime.h>

// Problem shape (fixed by the dataset)
#define BB 4096
#define TT 512
#define II 10
#define HH 32
#define XS 12   // padded x stride (10 -> 12, keeps 8B alignment for f32x2 loads)

// ---- f32x2 packed helpers (Blackwell FFMA2 path, PTX-only) ----
__device__ __forceinline__ unsigned long long pk2(float a, float b) {
    unsigned long long r;
    asm("mov.b64 %0, {%1,%2};" : "=l"(r) : "f"(a), "f"(b));
    return r;
}
__device__ __forceinline__ void fma2(unsigned long long& acc,
                                     unsigned long long a,
                                     unsigned long long b) {
    asm("fma.rn.f32x2 %0, %1, %2, %0;" : "+l"(acc) : "l"(a), "l"(b));
}
__device__ __forceinline__ float2 up2(unsigned long long v) {
    float2 f;
    asm("mov.b64 {%0,%1}, %2;" : "=f"(f.x), "=f"(f.y) : "l"(v));
    return f;
}

// ---- fast activations (ex2/rcp approx: rel err ~1e-6, well under 1e-3) ----
__device__ __forceinline__ float fast_sigmoid(float x) {
    float e, r;
    asm("ex2.approx.f32 %0, %1;" : "=f"(e) : "f"(-1.4426950408889634f * x));
    asm("rcp.approx.f32 %0, %1;" : "=f"(r) : "f"(1.0f + e));
    return r;
}
__device__ __forceinline__ float fast_tanh(float x) {
    return 2.0f * fast_sigmoid(2.0f * x) - 1.0f;
}

__global__ void __launch_bounds__(128, 6) lstm_kernel(
    const float* __restrict__ x,     const float* __restrict__ h0,
    const float* __restrict__ c0,    const float* __restrict__ W_ih,
    const float* __restrict__ W_hh,  const float* __restrict__ b_ih,
    const float* __restrict__ b_hh,  const float* __restrict__ W_lin,
    const float* __restrict__ b_lin, float* __restrict__ out)
{
    __shared__ __align__(16) float x_sh[TT * XS];   // 24576 B
    __shared__ __align__(16) float h_sh[HH];
    __shared__ __align__(16) float gates_sh[4 * HH];

    const int r = threadIdx.x;          // gate row 0..127
    const int b = blockIdx.x;           // batch element
    const int g = r >> 5;               // gate index: 0=i 1=f 2=g 3=o

    // ---- load this row's weights into registers, packed as f32x2 pairs ----
    unsigned long long whh[HH / 2];
    {
        const float2* wrow = reinterpret_cast<const float2*>(W_hh + r * HH);
        #pragma unroll
        for (int k = 0; k < HH / 2; k++) {
            float2 w = wrow[k];
            whh[k] = pk2(w.x, w.y);
        }
    }
    unsigned long long wih[XS / 2];
    {
        const float* wrow = W_ih + r * II;
        #pragma unroll
        for (int p = 0; p < II / 2; p++) wih[p] = pk2(wrow[2 * p], wrow[2 * p + 1]);
        wih[5] = pk2(0.0f, 0.0f);   // pad pair (matches x_sh padding)
    }
    const float bias = b_ih[r] + b_hh[r];

    // ---- stage this batch element's x into padded SMEM ----
    {
        const float* xb = x + (size_t)b * (TT * II);
        for (int idx = r; idx < TT * XS; idx += 128) {
            int t = idx / XS;
            int i = idx - t * XS;
            x_sh[idx] = (i < II) ? xb[t * II + i] : 0.0f;
        }
    }

    // ---- init h, c (c lives in warp-0 registers only) ----
    float c_reg = 0.0f;
    float h_reg = 0.0f;
    if (r < HH) {
        h_reg = h0[b * HH + r];
        c_reg = c0[b * HH + r];
        h_sh[r] = h_reg;
    }
    __syncthreads();

    const unsigned long long* hp =
        reinterpret_cast<const unsigned long long*>(h_sh);

    // ---- recurrence ----
    for (int t = 0; t < TT; t++) {
        unsigned long long a0 = pk2(0.0f, 0.0f);
        unsigned long long a1 = pk2(0.0f, 0.0f);

        #pragma unroll
        for (int k = 0; k < HH / 2; k += 2) {
            fma2(a0, whh[k],     hp[k]);
            fma2(a1, whh[k + 1], hp[k + 1]);
        }
        const unsigned long long* xp =
            reinterpret_cast<const unsigned long long*>(x_sh + t * XS);
        #pragma unroll
        for (int p = 0; p < XS / 2; p += 2) {
            fma2(a0, wih[p],     xp[p]);
            fma2(a1, wih[p + 1], xp[p + 1]);
        }

        float2 f0 = up2(a0), f1 = up2(a1);
        float gate = (f0.x + f1.x) + (f0.y + f1.y) + bias;

        // warp-uniform branch (g is constant per warp)
        float act = (g == 2) ? fast_tanh(gate) : fast_sigmoid(gate);
        gates_sh[r] = act;
        __syncthreads();   // gates visible; all old-h reads complete

        if (r < HH) {
            float iv = gates_sh[r];
            float fv = gates_sh[HH + r];
            float gv = gates_sh[2 * HH + r];
            float ov = gates_sh[3 * HH + r];
            c_reg = fv * c_reg + iv * gv;
            h_reg = ov * fast_tanh(c_reg);
            h_sh[r] = h_reg;
        }
        __syncthreads();   // new h visible for next step
    }

    // ---- final linear head: out[b] = hT . W_lin + b_lin ----
    if (r < HH) {
        float v = h_reg * W_lin[r];
        #pragma unroll
        for (int off = 16; off > 0; off >>= 1)
            v += __shfl_xor_sync(0xffffffffu, v, off);
        if (r == 0) out[b] = v + b_lin[0];
    }
}

extern "C" void kernel_launch(void* const* d_in, const int* in_sizes, int n_in,
                              void* d_out, int out_size) {
    const float* x     = (const float*)d_in[0];
    const float* h0    = (const float*)d_in[1];
    const float* c0    = (const float*)d_in[2];
    const float* W_ih  = (const float*)d_in[3];
    const float* W_hh  = (const float*)d_in[4];
    const float* b_ih  = (const float*)d_in[5];
    const float* b_hh  = (const float*)d_in[6];
    const float* W_lin = (const float*)d_in[7];
    const float* b_lin = (const float*)d_in[8];
    float* out = (float*)d_out;

    int B = in_sizes[1] / HH;   // 4096
    lstm_kernel<<<B, 128>>>(x, h0, c0, W_ih, W_hh, b_ih, b_hh, W_lin, b_lin, out);
}

// round 2
// speedup vs baseline: 1.1062x; 1.1062x over previous
#include <cuda_runtime.h>

// Problem shape (fixed by the dataset)
#define BB 4096
#define TT 512
#define II 10
#define HH 32
#define XS 12   // padded x stride (10 -> 12 floats, 48B = 3 x 16B aligned chunks)

typedef unsigned long long ull;

// ---- f32x2 packed helpers (Blackwell FFMA2 path, PTX-only) ----
__device__ __forceinline__ ull pk2(float a, float b) {
    ull r;
    asm("mov.b64 %0, {%1,%2};" : "=l"(r) : "f"(a), "f"(b));
    return r;
}
__device__ __forceinline__ void fma2(ull& acc, ull a, ull b) {
    asm("fma.rn.f32x2 %0, %1, %2, %0;" : "+l"(acc) : "l"(a), "l"(b));
}
__device__ __forceinline__ float2 up2(ull v) {
    float2 f;
    asm("mov.b64 {%0,%1}, %2;" : "=f"(f.x), "=f"(f.y) : "l"(v));
    return f;
}

// ---- fast activations (ex2/rcp approx: rel err ~1e-6, well under 1e-3) ----
__device__ __forceinline__ float fast_sigmoid(float x) {
    float e, r;
    asm("ex2.approx.f32 %0, %1;" : "=f"(e) : "f"(-1.4426950408889634f * x));
    asm("rcp.approx.f32 %0, %1;" : "=f"(r) : "f"(1.0f + e));
    return r;
}
__device__ __forceinline__ float fast_tanh(float x) {
    return 2.0f * fast_sigmoid(2.0f * x) - 1.0f;
}

// 64 threads per block, one batch element per block.
// Thread r owns gate rows r and r+64:
//   warp 0 (r 0..31):  rows 0..31  (i, sigmoid)  and 64..95  (g, tanh)
//   warp 1 (r 32..63): rows 32..63 (f, sigmoid)  and 96..127 (o, sigmoid)
__global__ void __launch_bounds__(64, 8) lstm_kernel(
    const float* __restrict__ x,     const float* __restrict__ h0,
    const float* __restrict__ c0,    const float* __restrict__ W_ih,
    const float* __restrict__ W_hh,  const float* __restrict__ b_ih,
    const float* __restrict__ b_hh,  const float* __restrict__ W_lin,
    const float* __restrict__ b_lin, float* __restrict__ out)
{
    __shared__ __align__(16) float x_sh[TT * XS];   // 24576 B
    __shared__ __align__(16) float h_sh[HH];
    __shared__ __align__(16) float gates_sh[4 * HH];

    const int r  = threadIdx.x;      // 0..63
    const int b  = blockIdx.x;       // batch element
    const int r1 = r + 64;           // second gate row

    // ---- load both rows' weights into registers, packed as f32x2 pairs ----
    ull whh0[HH / 2], whh1[HH / 2];
    {
        const float2* w0 = reinterpret_cast<const float2*>(W_hh + r  * HH);
        const float2* w1 = reinterpret_cast<const float2*>(W_hh + r1 * HH);
        #pragma unroll
        for (int k = 0; k < HH / 2; k++) {
            float2 a = w0[k]; whh0[k] = pk2(a.x, a.y);
            float2 c = w1[k]; whh1[k] = pk2(c.x, c.y);
        }
    }
    ull wih0[XS / 2], wih1[XS / 2];
    {
        const float* w0 = W_ih + r  * II;
        const float* w1 = W_ih + r1 * II;
        #pragma unroll
        for (int p = 0; p < II / 2; p++) {
            wih0[p] = pk2(w0[2 * p], w0[2 * p + 1]);
            wih1[p] = pk2(w1[2 * p], w1[2 * p + 1]);
        }
        wih0[5] = pk2(0.0f, 0.0f);   // pad pair (matches x_sh padding)
        wih1[5] = pk2(0.0f, 0.0f);
    }
    const float bias0 = b_ih[r]  + b_hh[r];
    const float bias1 = b_ih[r1] + b_hh[r1];

    // ---- stage this batch element's x into padded SMEM (float2 granularity) ----
    {
        const float2* xb = reinterpret_cast<const float2*>(x + (size_t)b * (TT * II));
        float2* xs = reinterpret_cast<float2*>(x_sh);
        // pair index p covers t = p/6, j = p%6; j<5 -> real data, j==5 -> zero pad
        for (int p = r; p < TT * XS / 2; p += 64) {
            int t = p / 6;
            int j = p - t * 6;
            xs[p] = (j < 5) ? xb[t * 5 + j] : make_float2(0.0f, 0.0f);
        }
    }

    // ---- init h, c (c lives in warp-0 registers only) ----
    float c_reg = 0.0f;
    float h_reg = 0.0f;
    if (r < HH) {
        h_reg = h0[b * HH + r];
        c_reg = c0[b * HH + r];
        h_sh[r] = h_reg;
    }
    __syncthreads();

    const ulonglong2* hp = reinterpret_cast<const ulonglong2*>(h_sh);
    const bool warp0 = (r < 32);     // warp-uniform

    // ---- recurrence ----
    for (int t = 0; t < TT; t++) {
        ull a0 = pk2(0.0f, 0.0f), a1 = pk2(0.0f, 0.0f);   // row r accumulators
        ull b0 = pk2(0.0f, 0.0f), b1 = pk2(0.0f, 0.0f);   // row r+64 accumulators

        #pragma unroll
        for (int k = 0; k < HH / 4; k++) {                // 8 x LDS.128 of h
            ulonglong2 h2 = hp[k];
            fma2(a0, whh0[2 * k],     h2.x);
            fma2(a1, whh0[2 * k + 1], h2.y);
            fma2(b0, whh1[2 * k],     h2.x);
            fma2(b1, whh1[2 * k + 1], h2.y);
        }
        const ulonglong2* xp =
            reinterpret_cast<const ulonglong2*>(x_sh + t * XS);
        #pragma unroll
        for (int p = 0; p < XS / 4; p++) {                // 3 x LDS.128 of x
            ulonglong2 x2 = xp[p];
            fma2(a0, wih0[2 * p],     x2.x);
            fma2(a1, wih0[2 * p + 1], x2.y);
            fma2(b0, wih1[2 * p],     x2.x);
            fma2(b1, wih1[2 * p + 1], x2.y);
        }

        float2 fa0 = up2(a0), fa1 = up2(a1);
        float2 fb0 = up2(b0), fb1 = up2(b1);
        float gate0 = (fa0.x + fa1.x) + (fa0.y + fa1.y) + bias0;
        float gate1 = (fb0.x + fb1.x) + (fb0.y + fb1.y) + bias1;

        float act0 = fast_sigmoid(gate0);                       // rows 0..63: i,f
        float act1 = warp0 ? fast_tanh(gate1)                   // rows 64..95: g
                           : fast_sigmoid(gate1);               // rows 96..127: o
        gates_sh[r]  = act0;
        gates_sh[r1] = act1;
        __syncthreads();   // gates visible; all old-h reads complete

        if (warp0) {
            float iv = gates_sh[r];
            float fv = gates_sh[HH + r];
            float gv = gates_sh[2 * HH + r];
            float ov = gates_sh[3 * HH + r];
            c_reg = fv * c_reg + iv * gv;
            h_reg = ov * fast_tanh(c_reg);
            h_sh[r] = h_reg;
        }
        __syncthreads();   // new h visible for next step
    }

    // ---- final linear head: out[b] = hT . W_lin + b_lin ----
    if (warp0) {
        float v = h_reg * W_lin[r];
        #pragma unroll
        for (int off = 16; off > 0; off >>= 1)
            v += __shfl_xor_sync(0xffffffffu, v, off);
        if (r == 0) out[b] = v + b_lin[0];
    }
}

extern "C" void kernel_launch(void* const* d_in, const int* in_sizes, int n_in,
                              void* d_out, int out_size) {
    const float* x     = (const float*)d_in[0];
    const float* h0    = (const float*)d_in[1];
    const float* c0    = (const float*)d_in[2];
    const float* W_ih  = (const float*)d_in[3];
    const float* W_hh  = (const float*)d_in[4];
    const float* b_ih  = (const float*)d_in[5];
    const float* b_hh  = (const float*)d_in[6];
    const float* W_lin = (const float*)d_in[7];
    const float* b_lin = (const float*)d_in[8];
    float* out = (float*)d_out;

    int B = in_sizes[1] / HH;   // 4096
    lstm_kernel<<<B, 64>>>(x, h0, c0, W_ih, W_hh, b_ih, b_hh, W_lin, b_lin, out);
}

// round 3
// speedup vs baseline: 1.6783x; 1.5171x over previous
#include <cuda_runtime.h>

// Problem shape (fixed by the dataset)
#define TT 512
#define II 10
#define HH 32
#define XS 12          // padded x row stride in SMEM (floats): 48B, 16B-aligned
#define CH 128         // timesteps per x chunk
#define NCH (TT / CH)  // 4 chunks

typedef unsigned long long ull;

// ---- f32x2 packed helpers (Blackwell FFMA2 path, PTX-only) ----
__device__ __forceinline__ ull pk2(float a, float b) {
    ull r;
    asm("mov.b64 %0, {%1,%2};" : "=l"(r) : "f"(a), "f"(b));
    return r;
}
__device__ __forceinline__ void fma2(ull& acc, ull a, ull b) {
    asm("fma.rn.f32x2 %0, %1, %2, %0;" : "+l"(acc) : "l"(a), "l"(b));
}
__device__ __forceinline__ float2 up2(ull v) {
    float2 f;
    asm("mov.b64 {%0,%1}, %2;" : "=f"(f.x), "=f"(f.y) : "l"(v));
    return f;
}

// ---- MUFU.TANH (sm_75+): 1 MUFU per activation ----
__device__ __forceinline__ float fast_tanh(float x) {
    float r;
    asm("tanh.approx.f32 %0, %1;" : "=f"(r) : "f"(x));
    return r;
}

__device__ __forceinline__ unsigned smem_u32(const void* p) {
    return (unsigned)__cvta_generic_to_shared(p);
}
__device__ __forceinline__ void cp8(unsigned dst, const void* src) {
    asm volatile("cp.async.ca.shared.global [%0], [%1], 8;" :: "r"(dst), "l"(src));
}

// 64 threads per block; block handles TWO batch elements (2*blockIdx, 2*blockIdx+1).
// Thread r owns gate rows r and r+64 for BOTH elements (same weight registers).
//   warp 0 (r 0..31):  rows 0..31  (i, sigmoid)  and 64..95  (g, tanh)
//   warp 1 (r 32..63): rows 32..63 (f, sigmoid)  and 96..127 (o, sigmoid)
// Sigmoid rows have weights/bias pre-scaled by 0.5: sigm(x) = 0.5*tanh(0.5x)+0.5.
// Warp e performs the c/h elementwise update for element e.
__global__ void __launch_bounds__(64, 8) lstm_kernel(
    const float* __restrict__ x,     const float* __restrict__ h0,
    const float* __restrict__ c0,    const float* __restrict__ W_ih,
    const float* __restrict__ W_hh,  const float* __restrict__ b_ih,
    const float* __restrict__ b_hh,  const float* __restrict__ W_lin,
    const float* __restrict__ b_lin, float* __restrict__ out)
{
    __shared__ __align__(16) float x_sh[2][2][CH * XS];   // [buf][elem] = 24576 B
    __shared__ __align__(16) float h_sh[2][HH];           // [elem]
    __shared__ __align__(16) float gates_sh[2][4 * HH];   // [elem][idx*4 + gate]

    const int r  = threadIdx.x;          // 0..63
    const int l  = r & 31;               // h-index within gate
    const int g0 = r >> 5;               // warp id; first-row gate (0=i or 1=f)
    const int b0 = blockIdx.x * 2;
    const int b1 = b0 + 1;
    const int r1 = r + 64;               // second gate row (g or o)

    const float s0 = 0.5f;                          // rows i/f: sigmoid
    const float s1 = (g0 == 0) ? 1.0f : 0.5f;       // row g: tanh; row o: sigmoid

    // ---- weights into registers, pre-scaled, packed f32x2 ----
    ull whh0[16], whh1[16];
    {
        const float2* w0 = reinterpret_cast<const float2*>(W_hh + r  * HH);
        const float2* w1 = reinterpret_cast<const float2*>(W_hh + r1 * HH);
        #pragma unroll
        for (int k = 0; k < 16; k++) {
            float2 a = w0[k]; whh0[k] = pk2(a.x * s0, a.y * s0);
            float2 c = w1[k]; whh1[k] = pk2(c.x * s1, c.y * s1);
        }
    }
    ull wih0[5], wih1[5];
    {
        const float* u0 = W_ih + r  * II;
        const float* u1 = W_ih + r1 * II;
        #pragma unroll
        for (int p = 0; p < 5; p++) {
            wih0[p] = pk2(u0[2 * p] * s0, u0[2 * p + 1] * s0);
            wih1[p] = pk2(u1[2 * p] * s1, u1[2 * p + 1] * s1);
        }
    }
    const float bias0 = (b_ih[r]  + b_hh[r])  * s0;
    const float bias1 = (b_ih[r1] + b_hh[r1]) * s1;
    const float blin  = b_lin[0];

    // ---- init h, c; warp e owns element e's state ----
    const int be = g0 ? b1 : b0;
    float c_reg = c0[be * HH + l];
    float h_reg = h0[be * HH + l];
    h_sh[g0][l] = h_reg;

    // ---- x prefetch (cp.async double buffer) ----
    const float* xb0 = x + (size_t)b0 * (TT * II);
    const float* xb1 = x + (size_t)b1 * (TT * II);
    const unsigned d0base[2] = { smem_u32(&x_sh[0][0][0]), smem_u32(&x_sh[1][0][0]) };
    const unsigned d1base[2] = { smem_u32(&x_sh[0][1][0]), smem_u32(&x_sh[1][1][0]) };

    #define PREFETCH(chunk, buf)                                                \
        do {                                                                    \
            const float* sp0 = xb0 + (chunk) * CH * II;                         \
            const float* sp1 = xb1 + (chunk) * CH * II;                         \
            unsigned dd0 = d0base[buf], dd1 = d1base[buf];                      \
            for (int p = r; p < CH * 5; p += 64) {                              \
                int t = p / 5, j = p - t * 5;                                   \
                unsigned off = (unsigned)(t * XS + j * 2) * 4u;                 \
                const float* so = sp0 + t * II + j * 2;                         \
                const float* s1p = sp1 + t * II + j * 2;                        \
                cp8(dd0 + off, so);                                             \
                cp8(dd1 + off, s1p);                                            \
            }                                                                   \
            asm volatile("cp.async.commit_group;");                             \
        } while (0)

    PREFETCH(0, 0);
    asm volatile("cp.async.wait_group 0;");
    __syncthreads();

    // ---- recurrence ----
    for (int cix = 0; cix < NCH; cix++) {
        if (cix + 1 < NCH) { PREFETCH(cix + 1, (cix + 1) & 1); }
        const float* xc0 = x_sh[cix & 1][0];
        const float* xc1 = x_sh[cix & 1][1];

        for (int tt = 0; tt < CH; tt++) {
            // ===== element 0 gates =====
            ull a0 = 0ull, a1 = 0ull, e0 = 0ull, e1 = 0ull;
            {
                const ulonglong2* hp = reinterpret_cast<const ulonglong2*>(h_sh[0]);
                #pragma unroll
                for (int k = 0; k < 8; k++) {
                    ulonglong2 h2 = hp[k];
                    fma2(a0, whh0[2 * k],     h2.x);
                    fma2(a1, whh0[2 * k + 1], h2.y);
                    fma2(e0, whh1[2 * k],     h2.x);
                    fma2(e1, whh1[2 * k + 1], h2.y);
                }
                const ull* xq = reinterpret_cast<const ull*>(xc0 + tt * XS);
                const ulonglong2* xp = reinterpret_cast<const ulonglong2*>(xq);
                ulonglong2 x01 = xp[0], x23 = xp[1];
                ull x4 = xq[4];
                fma2(a0, wih0[0], x01.x); fma2(a1, wih0[1], x01.y);
                fma2(a0, wih0[2], x23.x); fma2(a1, wih0[3], x23.y);
                fma2(a0, wih0[4], x4);
                fma2(e0, wih1[0], x01.x); fma2(e1, wih1[1], x01.y);
                fma2(e0, wih1[2], x23.x); fma2(e1, wih1[3], x23.y);
                fma2(e0, wih1[4], x4);
            }
            // ===== element 1 gates =====
            ull f0 = 0ull, f1 = 0ull, k0 = 0ull, k1 = 0ull;
            {
                const ulonglong2* hp = reinterpret_cast<const ulonglong2*>(h_sh[1]);
                #pragma unroll
                for (int k = 0; k < 8; k++) {
                    ulonglong2 h2 = hp[k];
                    fma2(f0, whh0[2 * k],     h2.x);
                    fma2(f1, whh0[2 * k + 1], h2.y);
                    fma2(k0, whh1[2 * k],     h2.x);
                    fma2(k1, whh1[2 * k + 1], h2.y);
                }
                const ull* xq = reinterpret_cast<const ull*>(xc1 + tt * XS);
                const ulonglong2* xp = reinterpret_cast<const ulonglong2*>(xq);
                ulonglong2 x01 = xp[0], x23 = xp[1];
                ull x4 = xq[4];
                fma2(f0, wih0[0], x01.x); fma2(f1, wih0[1], x01.y);
                fma2(f0, wih0[2], x23.x); fma2(f1, wih0[3], x23.y);
                fma2(f0, wih0[4], x4);
                fma2(k0, wih1[0], x01.x); fma2(k1, wih1[1], x01.y);
                fma2(k0, wih1[2], x23.x); fma2(k1, wih1[3], x23.y);
                fma2(k0, wih1[4], x4);
            }

            float2 pa = up2(a0), pb = up2(a1);
            float2 pc = up2(e0), pd = up2(e1);
            float2 pe = up2(f0), pf = up2(f1);
            float2 pg = up2(k0), ph = up2(k1);
            float g00 = (pa.x + pa.y) + (pb.x + pb.y) + bias0;   // elem0 row r
            float g01 = (pc.x + pc.y) + (pd.x + pd.y) + bias1;   // elem0 row r1
            float g10 = (pe.x + pe.y) + (pf.x + pf.y) + bias0;   // elem1 row r
            float g11 = (pg.x + pg.y) + (ph.x + ph.y) + bias1;   // elem1 row r1

            float t00 = fast_tanh(g00), t01 = fast_tanh(g01);
            float t10 = fast_tanh(g10), t11 = fast_tanh(g11);
            float act00 = fmaf(0.5f, t00, 0.5f);                 // i or f: sigmoid
            float act10 = fmaf(0.5f, t10, 0.5f);
            float act01 = (g0 == 0) ? t01 : fmaf(0.5f, t01, 0.5f);  // g : o
            float act11 = (g0 == 0) ? t11 : fmaf(0.5f, t11, 0.5f);

            gates_sh[0][l * 4 + g0]     = act00;
            gates_sh[0][l * 4 + g0 + 2] = act01;
            gates_sh[1][l * 4 + g0]     = act10;
            gates_sh[1][l * 4 + g0 + 2] = act11;
            __syncthreads();   // gates visible; all old-h reads complete

            {   // warp g0 updates element g0
                float4 gt = *reinterpret_cast<const float4*>(&gates_sh[g0][l * 4]);
                // gt.x = i, gt.y = f, gt.z = g, gt.w = o
                c_reg = fmaf(gt.y, c_reg, gt.x * gt.z);
                h_reg = gt.w * fast_tanh(c_reg);
                h_sh[g0][l] = h_reg;
            }
            __syncthreads();   // new h visible for next step
        }
        asm volatile("cp.async.wait_group 0;");
        __syncthreads();
    }

    // ---- final linear head: out[be] = h . W_lin + b_lin (warp e owns elem e) ----
    {
        float v = h_reg * W_lin[l];
        #pragma unroll
        for (int off = 16; off > 0; off >>= 1)
            v += __shfl_xor_sync(0xffffffffu, v, off);
        if (l == 0) out[be] = v + blin;
    }
}

extern "C" void kernel_launch(void* const* d_in, const int* in_sizes, int n_in,
                              void* d_out, int out_size) {
    const float* x     = (const float*)d_in[0];
    const float* h0    = (const float*)d_in[1];
    const float* c0    = (const float*)d_in[2];
    const float* W_ih  = (const float*)d_in[3];
    const float* W_hh  = (const float*)d_in[4];
    const float* b_ih  = (const float*)d_in[5];
    const float* b_hh  = (const float*)d_in[6];
    const float* W_lin = (const float*)d_in[7];
    const float* b_lin = (const float*)d_in[8];
    float* out = (float*)d_out;

    int B = in_sizes[1] / HH;   // 4096
    lstm_kernel<<<B / 2, 64>>>(x, h0, c0, W_ih, W_hh, b_ih, b_hh, W_lin, b_lin, out);
}